// round 1
// baseline (speedup 1.0000x reference)
#include <cuda_runtime.h>
#include <cuda_bf16.h>
#include <cstdint>

#define MAX_NODES 50000
#define MAX_EDGES 800000
#define IN_DIM    128
#define OUT_DIM   64
#define LEAKY     0.01f

// ---------------- scratch (device globals; no allocation allowed) ----------
__device__ float    g_z[MAX_NODES * OUT_DIM];     // projected features
__device__ float    g_azs[MAX_NODES];             // z . a[:64]
__device__ float    g_azd[MAX_NODES];             // z . a[64:]
__device__ unsigned g_emax[MAX_NODES];            // encoded segment max
__device__ float    g_esum[MAX_NODES];            // segment sum of exp
__device__ float    g_e[MAX_EDGES];               // leaky_relu scores
__device__ float    g_eexp[MAX_EDGES];            // exp(e - max)

// monotonic float<->uint encoding for atomicMax on floats (handles negatives)
__device__ __forceinline__ unsigned enc_f(float x) {
    unsigned b = __float_as_uint(x);
    return (b & 0x80000000u) ? ~b : (b | 0x80000000u);
}
__device__ __forceinline__ float dec_f(unsigned u) {
    unsigned b = (u & 0x80000000u) ? (u & 0x7FFFFFFFu) : ~u;
    return __uint_as_float(b);
}

// ---------------- kernel 0: init output + reduction buffers ----------------
__global__ void init_kernel(float* __restrict__ h, int n_nodes) {
    int i = blockIdx.x * blockDim.x + threadIdx.x;
    int total_h = n_nodes * OUT_DIM;
    // zero h with grid stride (float4)
    for (int t = i; t * 4 < total_h; t += gridDim.x * blockDim.x) {
        if (t * 4 + 3 < total_h)
            reinterpret_cast<float4*>(h)[t] = make_float4(0.f, 0.f, 0.f, 0.f);
    }
    for (int t = i; t < n_nodes; t += gridDim.x * blockDim.x) {
        g_emax[t] = 0u;     // encoded value below enc(-inf) = 0x007FFFFF
        g_esum[t] = 0.f;
    }
}

// ---------------- kernel 1: z = F @ W, az_src, az_dst ----------------------
__global__ void __launch_bounds__(128)
proj_kernel(const float* __restrict__ feat,
            const float* __restrict__ W,
            const float* __restrict__ a,
            int n_nodes) {
    __shared__ float Ws[IN_DIM * OUT_DIM];   // 32 KB
    __shared__ float as[2 * OUT_DIM];

    int tid = threadIdx.x;
    // cooperative load of W (float4) and a
    for (int i = tid * 4; i < IN_DIM * OUT_DIM; i += blockDim.x * 4)
        *reinterpret_cast<float4*>(&Ws[i]) =
            *reinterpret_cast<const float4*>(&W[i]);
    for (int i = tid; i < 2 * OUT_DIM; i += blockDim.x)
        as[i] = a[i];
    __syncthreads();

    int node = blockIdx.x * blockDim.x + tid;
    if (node >= n_nodes) return;

    float acc[OUT_DIM];
#pragma unroll
    for (int j = 0; j < OUT_DIM; j++) acc[j] = 0.f;

    const float4* f4 = reinterpret_cast<const float4*>(feat + (size_t)node * IN_DIM);
#pragma unroll 2
    for (int k4 = 0; k4 < IN_DIM / 4; k4++) {
        float4 f = f4[k4];
        int k = k4 * 4;
#pragma unroll
        for (int j = 0; j < OUT_DIM; j += 4) {
            float4 w0 = *reinterpret_cast<const float4*>(&Ws[(k + 0) * OUT_DIM + j]);
            float4 w1 = *reinterpret_cast<const float4*>(&Ws[(k + 1) * OUT_DIM + j]);
            float4 w2 = *reinterpret_cast<const float4*>(&Ws[(k + 2) * OUT_DIM + j]);
            float4 w3 = *reinterpret_cast<const float4*>(&Ws[(k + 3) * OUT_DIM + j]);
            acc[j + 0] += f.x * w0.x + f.y * w1.x + f.z * w2.x + f.w * w3.x;
            acc[j + 1] += f.x * w0.y + f.y * w1.y + f.z * w2.y + f.w * w3.y;
            acc[j + 2] += f.x * w0.z + f.y * w1.z + f.z * w2.z + f.w * w3.z;
            acc[j + 3] += f.x * w0.w + f.y * w1.w + f.z * w2.w + f.w * w3.w;
        }
    }

    float s0 = 0.f, s1 = 0.f;
#pragma unroll
    for (int j = 0; j < OUT_DIM; j++) {
        s0 += acc[j] * as[j];
        s1 += acc[j] * as[OUT_DIM + j];
    }
    g_azs[node] = s0;
    g_azd[node] = s1;

    float4* zout = reinterpret_cast<float4*>(g_z + (size_t)node * OUT_DIM);
#pragma unroll
    for (int j = 0; j < OUT_DIM; j += 4)
        zout[j / 4] = make_float4(acc[j], acc[j + 1], acc[j + 2], acc[j + 3]);
}

// ---------------- kernel 2: edge scores + segment max -----------------------
__global__ void edge_max_kernel(const int* __restrict__ src,
                                const int* __restrict__ dst,
                                int n_edges) {
    int t = blockIdx.x * blockDim.x + threadIdx.x;
    if (t >= n_edges) return;
    int s = src[t], d = dst[t];
    float e = g_azs[s] + g_azd[d];
    e = (e > 0.f) ? e : LEAKY * e;
    g_e[t] = e;
    atomicMax(&g_emax[d], enc_f(e));
}

// ---------------- kernel 3: exp + segment sum --------------------------------
__global__ void edge_exp_kernel(const int* __restrict__ dst, int n_edges) {
    int t = blockIdx.x * blockDim.x + threadIdx.x;
    if (t >= n_edges) return;
    int d = dst[t];
    float w = __expf(g_e[t] - dec_f(g_emax[d]));
    g_eexp[t] = w;
    atomicAdd(&g_esum[d], w);
}

// ---------------- kernel 4: weighted scatter aggregation ---------------------
// 16 threads per edge, each owns a 4-float chunk of the 64-dim row.
__global__ void scatter_kernel(const int* __restrict__ src,
                               const int* __restrict__ dst,
                               float* __restrict__ h,
                               int n_edges) {
    long long t = (long long)blockIdx.x * blockDim.x + threadIdx.x;
    int edge = (int)(t >> 4);
    int part = (int)(t & 15);
    if (edge >= n_edges) return;

    int s = src[edge], d = dst[edge];
    float alpha = g_eexp[edge] / g_esum[d];

    float4 v = *reinterpret_cast<const float4*>(g_z + (size_t)s * OUT_DIM + part * 4);
    v.x *= alpha; v.y *= alpha; v.z *= alpha; v.w *= alpha;

    float* out = h + (size_t)d * OUT_DIM + part * 4;
    asm volatile("red.global.add.v4.f32 [%0], {%1, %2, %3, %4};"
                 :: "l"(out), "f"(v.x), "f"(v.y), "f"(v.z), "f"(v.w)
                 : "memory");
}

// ---------------- launch ------------------------------------------------------
extern "C" void kernel_launch(void* const* d_in, const int* in_sizes, int n_in,
                              void* d_out, int out_size) {
    const float* feat = (const float*)d_in[0];
    const int*   src  = (const int*)  d_in[1];
    const int*   dst  = (const int*)  d_in[2];
    const float* W    = (const float*)d_in[3];
    const float* a    = (const float*)d_in[4];
    float* h = (float*)d_out;

    int n_nodes = in_sizes[0] / IN_DIM;
    int n_edges = in_sizes[1];

    // init
    {
        int threads = 256;
        int blocks = 1024;
        init_kernel<<<blocks, threads>>>(h, n_nodes);
    }
    // projection
    {
        int threads = 128;
        int blocks = (n_nodes + threads - 1) / threads;
        proj_kernel<<<blocks, threads>>>(feat, W, a, n_nodes);
    }
    // edge max
    {
        int threads = 256;
        int blocks = (n_edges + threads - 1) / threads;
        edge_max_kernel<<<blocks, threads>>>(src, dst, n_edges);
    }
    // edge exp + sum
    {
        int threads = 256;
        int blocks = (n_edges + threads - 1) / threads;
        edge_exp_kernel<<<blocks, threads>>>(dst, n_edges);
    }
    // scatter
    {
        long long total = (long long)n_edges * 16;
        int threads = 256;
        int blocks = (int)((total + threads - 1) / threads);
        scatter_kernel<<<blocks, threads>>>(src, dst, h, n_edges);
    }
}

// round 2
// speedup vs baseline: 1.1557x; 1.1557x over previous
#include <cuda_runtime.h>
#include <cuda_bf16.h>
#include <cstdint>

#define MAX_NODES 50048
#define MAX_EDGES 800000
#define IN_DIM    128
#define OUT_DIM   64
#define LEAKY     0.01f
#define SCAN_BLK  1024
#define MAX_PARTS ((MAX_NODES + SCAN_BLK - 1) / SCAN_BLK)

// ---------------- scratch (device globals; no allocation allowed) ----------
__device__ float g_z[MAX_NODES * OUT_DIM];     // projected features
__device__ float g_azs[MAX_NODES];             // z . a[:64]
__device__ float g_azd[MAX_NODES];             // z . a[64:]
__device__ int   g_cnt[MAX_NODES];             // per-dst degree
__device__ int   g_off[MAX_NODES];             // exclusive offset (within scan block)
__device__ int   g_cursor[MAX_NODES];          // fill cursors
__device__ int   g_part[MAX_PARTS];            // scan block sums
__device__ int   g_partoff[MAX_PARTS];         // scanned block offsets
__device__ int   g_srcperm[MAX_EDGES];         // CSR: src per slot
__device__ float g_wperm[MAX_EDGES];           // CSR: exp(e) per slot

// ---------------- kernel 0: zero counters ----------------------------------
__global__ void init_kernel(int n_nodes) {
    int i = blockIdx.x * blockDim.x + threadIdx.x;
    if (i < n_nodes) {
        g_cnt[i] = 0;
        g_cursor[i] = 0;
    }
}

// ---------------- kernel 1: z = F @ W, az_src, az_dst ----------------------
__global__ void __launch_bounds__(128)
proj_kernel(const float* __restrict__ feat,
            const float* __restrict__ W,
            const float* __restrict__ a,
            int n_nodes) {
    __shared__ float Ws[IN_DIM * OUT_DIM];   // 32 KB
    __shared__ float as[2 * OUT_DIM];

    int tid = threadIdx.x;
    for (int i = tid * 4; i < IN_DIM * OUT_DIM; i += blockDim.x * 4)
        *reinterpret_cast<float4*>(&Ws[i]) =
            *reinterpret_cast<const float4*>(&W[i]);
    for (int i = tid; i < 2 * OUT_DIM; i += blockDim.x)
        as[i] = a[i];
    __syncthreads();

    int node = blockIdx.x * blockDim.x + tid;
    if (node >= n_nodes) return;

    float acc[OUT_DIM];
#pragma unroll
    for (int j = 0; j < OUT_DIM; j++) acc[j] = 0.f;

    const float4* f4 = reinterpret_cast<const float4*>(feat + (size_t)node * IN_DIM);
#pragma unroll 2
    for (int k4 = 0; k4 < IN_DIM / 4; k4++) {
        float4 f = f4[k4];
        int k = k4 * 4;
#pragma unroll
        for (int j = 0; j < OUT_DIM; j += 4) {
            float4 w0 = *reinterpret_cast<const float4*>(&Ws[(k + 0) * OUT_DIM + j]);
            float4 w1 = *reinterpret_cast<const float4*>(&Ws[(k + 1) * OUT_DIM + j]);
            float4 w2 = *reinterpret_cast<const float4*>(&Ws[(k + 2) * OUT_DIM + j]);
            float4 w3 = *reinterpret_cast<const float4*>(&Ws[(k + 3) * OUT_DIM + j]);
            acc[j + 0] += f.x * w0.x + f.y * w1.x + f.z * w2.x + f.w * w3.x;
            acc[j + 1] += f.x * w0.y + f.y * w1.y + f.z * w2.y + f.w * w3.y;
            acc[j + 2] += f.x * w0.z + f.y * w1.z + f.z * w2.z + f.w * w3.z;
            acc[j + 3] += f.x * w0.w + f.y * w1.w + f.z * w2.w + f.w * w3.w;
        }
    }

    float s0 = 0.f, s1 = 0.f;
#pragma unroll
    for (int j = 0; j < OUT_DIM; j++) {
        s0 += acc[j] * as[j];
        s1 += acc[j] * as[OUT_DIM + j];
    }
    g_azs[node] = s0;
    g_azd[node] = s1;

    float4* zout = reinterpret_cast<float4*>(g_z + (size_t)node * OUT_DIM);
#pragma unroll
    for (int j = 0; j < OUT_DIM; j += 4)
        zout[j / 4] = make_float4(acc[j], acc[j + 1], acc[j + 2], acc[j + 3]);
}

// ---------------- kernel 2: per-dst degree histogram ------------------------
__global__ void count_kernel(const int* __restrict__ dst, int n_edges) {
    int t = blockIdx.x * blockDim.x + threadIdx.x;
    if (t < n_edges) atomicAdd(&g_cnt[dst[t]], 1);
}

// ---------------- kernel 3a: block-level exclusive scan ----------------------
__global__ void __launch_bounds__(SCAN_BLK)
scan1_kernel(int n) {
    int tid = threadIdx.x;
    int i = blockIdx.x * SCAN_BLK + tid;
    int v = (i < n) ? g_cnt[i] : 0;

    int x = v;
#pragma unroll
    for (int o = 1; o < 32; o <<= 1) {
        int y = __shfl_up_sync(0xffffffffu, x, o);
        if ((tid & 31) >= o) x += y;
    }
    __shared__ int wsum[32];
    if ((tid & 31) == 31) wsum[tid >> 5] = x;
    __syncthreads();
    if (tid < 32) {
        int w = wsum[tid];
#pragma unroll
        for (int o = 1; o < 32; o <<= 1) {
            int y = __shfl_up_sync(0xffffffffu, w, o);
            if (tid >= o) w += y;
        }
        wsum[tid] = w;
    }
    __syncthreads();
    int warpoff = (tid >= 32) ? wsum[(tid >> 5) - 1] : 0;
    int incl = x + warpoff;
    if (i < n) g_off[i] = incl - v;
    if (tid == SCAN_BLK - 1) g_part[blockIdx.x] = incl;
}

// ---------------- kernel 3b: scan of block sums (single block) --------------
__global__ void __launch_bounds__(64)
scan2_kernel(int nparts) {
    int tid = threadIdx.x;
    int v = (tid < nparts) ? g_part[tid] : 0;
    int x = v;
#pragma unroll
    for (int o = 1; o < 32; o <<= 1) {
        int y = __shfl_up_sync(0xffffffffu, x, o);
        if ((tid & 31) >= o) x += y;
    }
    __shared__ int ws[2];
    if ((tid & 31) == 31) ws[tid >> 5] = x;
    __syncthreads();
    int off = (tid >= 32) ? ws[0] : 0;
    if (tid < nparts) g_partoff[tid] = x + off - v;
}

// ---------------- kernel 4: compute edge weights + CSR fill ------------------
__global__ void fill_kernel(const int* __restrict__ src,
                            const int* __restrict__ dst,
                            int n_edges) {
    int t = blockIdx.x * blockDim.x + threadIdx.x;
    if (t >= n_edges) return;
    int s = src[t], d = dst[t];
    float e = g_azs[s] + g_azd[d];
    e = (e > 0.f) ? e : LEAKY * e;
    float w = __expf(e);
    int pos = g_off[d] + g_partoff[d >> 10] + atomicAdd(&g_cursor[d], 1);
    g_srcperm[pos] = s;
    g_wperm[pos]   = w;
}

// ---------------- kernel 5: one warp per destination node --------------------
__global__ void __launch_bounds__(256)
scatter_kernel(float* __restrict__ h, int n_nodes) {
    int warp_id = (blockIdx.x * blockDim.x + threadIdx.x) >> 5;
    int lane = threadIdx.x & 31;
    if (warp_id >= n_nodes) return;
    int node = warp_id;

    int start = g_off[node] + g_partoff[node >> 10];
    int cnt = g_cnt[node];

    float acc0 = 0.f, acc1 = 0.f, wsum = 0.f;

    for (int base = 0; base < cnt; base += 32) {
        int rem = cnt - base;
        int idx = base + lane;
        int s = 0; float w = 0.f;
        if (idx < cnt) {
            s = g_srcperm[start + idx];
            w = g_wperm[start + idx];
        }
        if (rem >= 32) {
#pragma unroll
            for (int j = 0; j < 32; j++) {
                int ss = __shfl_sync(0xffffffffu, s, j);
                float ww = __shfl_sync(0xffffffffu, w, j);
                wsum += ww;
                acc0 += ww * g_z[(size_t)ss * OUT_DIM + lane];
                acc1 += ww * g_z[(size_t)ss * OUT_DIM + 32 + lane];
            }
        } else {
            for (int j = 0; j < rem; j++) {
                int ss = __shfl_sync(0xffffffffu, s, j);
                float ww = __shfl_sync(0xffffffffu, w, j);
                wsum += ww;
                acc0 += ww * g_z[(size_t)ss * OUT_DIM + lane];
                acc1 += ww * g_z[(size_t)ss * OUT_DIM + 32 + lane];
            }
        }
    }

    float inv = (cnt > 0) ? 1.f / wsum : 0.f;
    h[(size_t)node * OUT_DIM + lane]      = acc0 * inv;
    h[(size_t)node * OUT_DIM + 32 + lane] = acc1 * inv;
}

// ---------------- launch ------------------------------------------------------
extern "C" void kernel_launch(void* const* d_in, const int* in_sizes, int n_in,
                              void* d_out, int out_size) {
    const float* feat = (const float*)d_in[0];
    const int*   src  = (const int*)  d_in[1];
    const int*   dst  = (const int*)  d_in[2];
    const float* W    = (const float*)d_in[3];
    const float* a    = (const float*)d_in[4];
    float* h = (float*)d_out;

    int n_nodes = in_sizes[0] / IN_DIM;
    int n_edges = in_sizes[1];
    int nparts = (n_nodes + SCAN_BLK - 1) / SCAN_BLK;

    // zero counters / cursors
    init_kernel<<<(n_nodes + 255) / 256, 256>>>(n_nodes);
    // projection + attention dot products
    proj_kernel<<<(n_nodes + 127) / 128, 128>>>(feat, W, a, n_nodes);
    // degree histogram
    count_kernel<<<(n_edges + 255) / 256, 256>>>(dst, n_edges);
    // two-level exclusive scan
    scan1_kernel<<<nparts, SCAN_BLK>>>(n_nodes);
    scan2_kernel<<<1, 64>>>(nparts);
    // edge weights + CSR fill
    fill_kernel<<<(n_edges + 255) / 256, 256>>>(src, dst, n_edges);
    // per-destination warp reduction
    {
        int warps_per_block = 256 / 32;
        int blocks = (n_nodes + warps_per_block - 1) / warps_per_block;
        scatter_kernel<<<blocks, 256>>>(h, n_nodes);
    }
}